// round 2
// baseline (speedup 1.0000x reference)
#include <cuda_runtime.h>

#define BATCH 131072
#define NCH 16
#define NK 15
#define NZ 256
#define NCOUT 10
#define MAXREG 128
#define NBLK 296
#define NTHR 256

// ---------------- scratch (device globals; no allocation) ----------------
__device__ unsigned       g_seen[NCH][1024];            // 32768-bit set per channel (self-cleaned)
__device__ unsigned       g_maskw[BATCH * 8];           // packed masks: 2 channels per word
__device__ int            g_cnt[NCH];                   // #distinct masks per channel (<=121)
__device__ unsigned short g_maskOfRegion[NCH][MAXREG];  // region id -> mask
__device__ unsigned char  g_regionMap[NCH][32768];      // mask -> region id (only observed entries valid)
__device__ float          g_zreg[NCH][MAXREG][NZ];      // per-region half z-row
__device__ unsigned char  g_cross[8][MAXREG][MAXREG];   // argmax index per (c8, rA, rB)

// ------------- software grid barrier (monotonic; replay-safe) -------------
__device__ unsigned long long g_count = 0ull;
__device__ unsigned           g_gen   = 0u;

__device__ __forceinline__ void gsync() {
    __syncthreads();
    if (threadIdx.x == 0) {
        __threadfence();
        unsigned my = *((volatile unsigned*)&g_gen);
        unsigned long long t = atomicAdd(&g_count, 1ull);
        if ((t % NBLK) == NBLK - 1) {
            __threadfence();
            atomicAdd(&g_gen, 1u);
        } else {
            while (*((volatile unsigned*)&g_gen) == my) __nanosleep(64);
        }
        __threadfence();
    }
    __syncthreads();
}

__global__ void __launch_bounds__(NTHR, 2) k_fused(
    const int* __restrict__ x, const float* __restrict__ lenLUT,
    const float* __restrict__ ipdLUT, const float* __restrict__ S,
    const float* __restrict__ H, const float* __restrict__ T,
    const float* __restrict__ LUT, float* __restrict__ out)
{
    __shared__ union ShU {
        struct { float S[NCH * 2 * NK]; float T[NCH * NK]; } p0;
        int   scan[NTHR];
        float zA[4][NZ];
    } sh;

    const int tid = threadIdx.x;

    // ================= Phase 0: per-element sign masks =================
    for (int i = tid; i < NCH * 2 * NK; i += NTHR) sh.p0.S[i] = S[i];
    for (int i = tid; i < NCH * NK;     i += NTHR) sh.p0.T[i] = T[i];
    __syncthreads();

    const float2* Lt = (const float2*)lenLUT;
    const float2* It = (const float2*)ipdLUT;

    for (int b = blockIdx.x * NTHR + tid; b < BATCH; b += NBLK * NTHR) {
        const int2* xp = (const int2*)x + (size_t)b * NCH;
        unsigned words[8];
        #pragma unroll
        for (int i = 0; i < 8; i++) {
            unsigned pair = 0;
            #pragma unroll
            for (int h = 0; h < 2; h++) {
                int c = 2 * i + h;
                int2   xv = xp[c];
                float2 l  = __ldg(&Lt[xv.x]);
                float2 p  = __ldg(&It[xv.y]);
                float  e0 = l.x + p.x;
                float  e1 = l.y + p.y;
                unsigned m = 0;
                #pragma unroll
                for (int k = 0; k < NK; k++) {
                    float dot = fmaf(e1, sh.p0.S[(c * 2 + 1) * NK + k],
                                     e0 * sh.p0.S[(c * 2) * NK + k]);
                    float y = (dot - sh.p0.T[c * NK + k]) - 1e-4f;
                    m |= (__float_as_uint(y) >> 31) << k;   // bit set <=> sign = -1
                }
                pair |= m << (16 * h);
                unsigned word = m >> 5, bit = 1u << (m & 31);
                // stale L1 read may only show 0 where true value is 1 -> harmless extra atomic
                if (!(g_seen[c][word] & bit)) atomicOr(&g_seen[c][word], bit);
            }
            words[i] = pair;
        }
        uint4* mp = (uint4*)&g_maskw[(size_t)b * 8];
        mp[0] = make_uint4(words[0], words[1], words[2], words[3]);
        mp[1] = make_uint4(words[4], words[5], words[6], words[7]);
    }
    gsync();

    // ================= Phase A: deterministic dedup + self-clean =================
    if (blockIdx.x < NCH) {
        int c = blockIdx.x;
        unsigned w[4]; int pc = 0;
        #pragma unroll
        for (int j = 0; j < 4; j++) {
            w[j] = __ldcg(&g_seen[c][tid * 4 + j]);   // L2-coherent past the atomics
            g_seen[c][tid * 4 + j] = 0u;              // self-clean for next launch
            pc += __popc(w[j]);
        }
        sh.scan[tid] = pc;
        __syncthreads();
        for (int off = 1; off < NTHR; off <<= 1) {    // Hillis-Steele inclusive scan
            int v = (tid >= off) ? sh.scan[tid - off] : 0;
            __syncthreads();
            sh.scan[tid] += v;
            __syncthreads();
        }
        int id = sh.scan[tid] - pc;                   // exclusive prefix
        if (tid == NTHR - 1) g_cnt[c] = min(sh.scan[tid], MAXREG);
        #pragma unroll
        for (int j = 0; j < 4; j++) {
            unsigned ww = w[j];
            unsigned base = (unsigned)(tid * 4 + j) << 5;
            while (ww) {
                int bb = __ffs(ww) - 1; ww &= ww - 1;
                unsigned mask = base | (unsigned)bb;
                if (id < MAXREG) {
                    g_regionMap[c][mask]  = (unsigned char)id;
                    g_maskOfRegion[c][id] = (unsigned short)mask;
                }
                id++;
            }
        }
    }
    gsync();

    // ================= Phase B: half z-rows per (channel, region) =================
    for (int task = blockIdx.x; task < NCH * MAXREG; task += NBLK) {
        int c = task >> 7, r = task & (MAXREG - 1);
        if (r >= g_cnt[c]) continue;
        unsigned m = g_maskOfRegion[c][r];
        int base = (c & 1) * NK;    // even channel -> H rows 0..14, odd -> 15..29
        float acc = 0.f;
        #pragma unroll
        for (int d = 0; d < NK; d++) {
            float hv = __ldg(&H[(base + d) * NZ + tid]);
            acc += ((m >> d) & 1) ? -hv : hv;
        }
        g_zreg[c][r][tid] = acc;
    }
    gsync();

    // ================= Phase C: argmax table, rA tiled x4 =================
    for (int task = blockIdx.x; task < 8 * (MAXREG / 4); task += NBLK) {
        int c8  = task >> 5;
        int rAt = task & 31;
        int cA = 2 * c8, cB = cA + 1;
        int nA = g_cnt[cA], nB = g_cnt[cB];
        int rA0 = rAt * 4;
        if (rA0 >= nA) continue;
        int na = min(4, nA - rA0);
        __syncthreads();
        for (int i = tid; i < 4 * NZ; i += NTHR) {
            int rr = i >> 8, k = i & 255;
            sh.zA[rr][k] = (rr < na) ? g_zreg[cA][rA0 + rr][k] : 0.f;
        }
        __syncthreads();
        int warp = tid >> 5, lane = tid & 31;
        for (int rB = warp; rB < nB; rB += 8) {
            const float* zb = &g_zreg[cB][rB][0];
            float zl[8];
            #pragma unroll
            for (int j = 0; j < 8; j++) zl[j] = zb[j * 32 + lane];
            #pragma unroll
            for (int i2 = 0; i2 < 4; i2++) {
                float best = __int_as_float(0xff800000);  // -inf
                int   bk = 0;
                #pragma unroll
                for (int j = 0; j < 8; j++) {
                    int k = j * 32 + lane;                // ascending per lane
                    float v = sh.zA[i2][k] + zl[j];
                    if (v > best) { best = v; bk = k; }
                }
                #pragma unroll
                for (int off = 16; off; off >>= 1) {      // first-index-wins warp argmax
                    float ov = __shfl_down_sync(0xffffffffu, best, off);
                    int   ok = __shfl_down_sync(0xffffffffu, bk, off);
                    if (ov > best || (ov == best && ok < bk)) { best = ov; bk = ok; }
                }
                if (lane == 0 && i2 < na) g_cross[c8][rA0 + i2][rB] = (unsigned char)bk;
            }
        }
    }
    gsync();

    // ================= Phase D: gather + log_softmax =================
    for (int b = blockIdx.x * NTHR + tid; b < BATCH; b += NBLK * NTHR) {
        const uint4* mp = (const uint4*)&g_maskw[(size_t)b * 8];
        uint4 m0 = mp[0], m1 = mp[1];
        unsigned mw[8] = {m0.x, m0.y, m0.z, m0.w, m1.x, m1.y, m1.z, m1.w};

        int r[NCH];
        #pragma unroll
        for (int i = 0; i < 8; i++) {
            r[2 * i]     = g_regionMap[2 * i][mw[i] & 0xffffu];
            r[2 * i + 1] = g_regionMap[2 * i + 1][mw[i] >> 16];
        }

        float acc[NCOUT];
        #pragma unroll
        for (int j = 0; j < NCOUT; j++) acc[j] = 0.f;

        #pragma unroll
        for (int c8 = 0; c8 < 8; c8++) {
            int idx = g_cross[c8][r[2 * c8]][r[2 * c8 + 1]];
            const float2* p = (const float2*)(LUT + (size_t)(c8 * 256 + idx) * NCOUT);
            #pragma unroll
            for (int j = 0; j < 5; j++) {
                float2 v = __ldg(&p[j]);
                acc[2 * j]     += v.x;
                acc[2 * j + 1] += v.y;
            }
        }

        float mx = acc[0];
        #pragma unroll
        for (int j = 1; j < NCOUT; j++) mx = fmaxf(mx, acc[j]);
        float s = 0.f;
        #pragma unroll
        for (int j = 0; j < NCOUT; j++) s += __expf(acc[j] - mx);
        float lg = __logf(s);

        float2* op = (float2*)(out + (size_t)b * NCOUT);
        #pragma unroll
        for (int j = 0; j < 5; j++)
            op[j] = make_float2((acc[2 * j] - mx) - lg, (acc[2 * j + 1] - mx) - lg);
    }
}

// ---------------- launch ----------------
extern "C" void kernel_launch(void* const* d_in, const int* in_sizes, int n_in,
                              void* d_out, int out_size) {
    const int*   x      = (const int*)d_in[0];
    const float* lenLUT = (const float*)d_in[1];
    const float* ipdLUT = (const float*)d_in[2];
    const float* S      = (const float*)d_in[3];
    const float* H      = (const float*)d_in[4];
    const float* T      = (const float*)d_in[5];
    const float* LUT    = (const float*)d_in[6];
    float*       out    = (float*)d_out;

    k_fused<<<NBLK, NTHR>>>(x, lenLUT, ipdLUT, S, H, T, LUT, out);
}